// round 1
// baseline (speedup 1.0000x reference)
#include <cuda_runtime.h>
#include <math.h>

#define TE   128   // edges per block
#define KH   128   // K half (HID=256 processed in 2 halves)
#define HIDD 256
#define EMBD 18
#define TNW  128   // N chunk width
#define KT   16    // k tile depth

typedef unsigned long long u64;

__device__ __forceinline__ u64 pack2s(float x) {
    u64 r; asm("mov.b64 %0, {%1, %1};" : "=l"(r) : "f"(x)); return r;
}
__device__ __forceinline__ void fma2(u64& d, u64 a, u64 b) {
    asm("fma.rn.f32x2 %0, %1, %2, %0;" : "+l"(d) : "l"(a), "l"(b));
}
__device__ __forceinline__ float2 unp2(u64 v) {
    float2 r; asm("mov.b64 {%0, %1}, %2;" : "=f"(r.x), "=f"(r.y) : "l"(v)); return r;
}
__device__ __forceinline__ void cp16(unsigned dst, const void* src) {
    asm volatile("cp.async.cg.shared.global [%0], [%1], 16;" :: "r"(dst), "l"(src));
}
__device__ __forceinline__ void cp_commit() { asm volatile("cp.async.commit_group;"); }
__device__ __forceinline__ void cp_wait0()  { asm volatile("cp.async.wait_group 0;"); }

// Shared memory layout (float offsets):
//  hs    [KH][TE]        0     (16384)
//  Lss   [TE][16]        16384 (2048)
//  Lvv   [TE][16]        18432 (2048)
//  Lsv   [TE][16]        20480 (2048)
//  Lvs   [TE][16][3]     22528 (6144)
//  y1s   [TE][4]         28672 (512)
//  osum  [TE][16]        29184 (2048)   } contiguous 10240-float
//  tsvs  [TE][16]        31232 (2048)   } accumulator region
//  rvss  [TE][16][3]     33280 (6144)   }
//  embs  [TE][18]        39424 (2304)
//  b2s   [1024]          41728 (1024)
//  uni   (w2s[2][16][128] | W1s[18][128]+b1s[128])  42752 (4096)
#define SMEM_FLOATS 46848

__global__ __launch_bounds__(256, 1)
void nequip_fused(const float* __restrict__ nodef,
                  const float* __restrict__ eattr,
                  const float* __restrict__ eemb,
                  const float* __restrict__ W1,
                  const float* __restrict__ b1,
                  const float* __restrict__ W2,
                  const float* __restrict__ b2,
                  const int* __restrict__ esrc,
                  const int* __restrict__ edst,
                  float* __restrict__ out,
                  int E, float scale_out)
{
    extern __shared__ float sm[];
    float* hs   = sm;
    float* Lss  = sm + 16384;
    float* Lvv  = sm + 18432;
    float* Lsv  = sm + 20480;
    float* Lvs  = sm + 22528;
    float* y1s  = sm + 28672;
    float* osum = sm + 29184;
    float* tsvs = sm + 31232;
    float* rvss = sm + 33280;
    float* embs = sm + 39424;
    float* b2s  = sm + 41728;
    float* w2s  = sm + 42752;          // gemm stage
    float* W1s  = sm + 42752;          // alias: stage-1 only
    float* b1s  = sm + 42752 + 2304;   // alias

    const int tid = threadIdx.x;
    const int tx = tid & 15, ty = tid >> 4;
    const int el = tid & 127, pp = tid >> 7;
    const int eb = blockIdx.x * TE;

    // ---- stage 0: constants, edge embeddings, zero accumulators ----
    #pragma unroll
    for (int i = tid; i < 1024; i += 256) b2s[i] = b2[i];
    for (int i = tid; i < TE * EMBD; i += 256) {
        int g = eb * EMBD + i;
        embs[i] = (g < E * EMBD) ? eemb[g] : 0.f;
    }
    for (int i = tid; i < 10240; i += 256) osum[i] = 0.f;  // osum..rvss contiguous

    // ---- stage 2: per-edge left vectors ----
    {
        const int eg = eb + el;
        if (eg < E) {
            const float inv3 = 0.57735026918962576451f;  // 1/sqrt(3)
            int src = esrc[eg];
            const float* x = nodef + (size_t)src * 64;
            float4 ya = *(const float4*)(eattr + (size_t)eg * 4);
            if (pp == 0) { y1s[el*4+0]=ya.y; y1s[el*4+1]=ya.z; y1s[el*4+2]=ya.w; }
            float4 s0 = *(const float4*)(x + pp*8);
            float4 s1 = *(const float4*)(x + pp*8 + 4);
            float svals[8] = {s0.x,s0.y,s0.z,s0.w,s1.x,s1.y,s1.z,s1.w};
            float vv[24];
            const float4* vx = (const float4*)(x + 16 + pp*24);
            #pragma unroll
            for (int q = 0; q < 6; q++) {
                float4 t = vx[q];
                vv[q*4]=t.x; vv[q*4+1]=t.y; vv[q*4+2]=t.z; vv[q*4+3]=t.w;
            }
            #pragma unroll
            for (int il = 0; il < 8; il++) {
                int i = pp*8 + il;
                Lss[el*16+i] = ya.x * svals[il];
                Lsv[el*16+i] = svals[il];
                float vd = ya.y*vv[il*3] + ya.z*vv[il*3+1] + ya.w*vv[il*3+2];
                Lvv[el*16+i] = inv3 * vd;
                Lvs[el*48 + i*3 + 0] = ya.x * vv[il*3];
                Lvs[el*48 + i*3 + 1] = ya.x * vv[il*3+1];
                Lvs[el*48 + i*3 + 2] = ya.x * vv[il*3+2];
            }
        }
    }

    for (int kh = 0; kh < 2; kh++) {
        __syncthreads();  // uni region free (prev gemm done), stage0/2 writes visible
        // load W1 half + b1 half into aliased region
        for (int i = tid; i < EMBD * KH; i += 256) {
            int t = i >> 7, c = i & 127;
            W1s[i] = W1[t * HIDD + kh * KH + c];
        }
        for (int i = tid; i < KH; i += 256) b1s[i] = b1[kh * KH + i];
        __syncthreads();

        // ---- stage 1: h = silu(emb @ W1 + b1), transposed into hs[c][e] ----
        {
            float er[EMBD];
            #pragma unroll
            for (int t = 0; t < EMBD; t++) er[t] = embs[el * EMBD + t];
            const int c0 = pp * 64;
            #pragma unroll 4
            for (int cl = 0; cl < 64; cl++) {
                int c = c0 + cl;
                float acc = b1s[c];
                #pragma unroll
                for (int t = 0; t < EMBD; t++) acc = fmaf(er[t], W1s[t*KH + c], acc);
                float sg = 1.f / (1.f + __expf(-acc));
                hs[c * TE + el] = acc * sg;
            }
        }
        __syncthreads();

        // ---- stage 3: GEMM over W2 chunks + immediate fold ----
        for (int chunk = 0; chunk < 8; chunk++) {
            const int n0 = chunk * TNW;
            u64 acc[8][4];
            #pragma unroll
            for (int i = 0; i < 8; i++)
                #pragma unroll
                for (int j = 0; j < 4; j++) acc[i][j] = 0ull;

            // preload tile 0 into buf 0
            {
                const int q0 = tid * 2;
                #pragma unroll
                for (int q = q0; q < q0 + 2; q++) {
                    int r = q >> 5, c = (q & 31) * 4;
                    const float* src = W2 + (size_t)(kh*KH + r) * 1024 + n0 + c;
                    unsigned dst = (unsigned)__cvta_generic_to_shared(&w2s[r*TNW + c]);
                    cp16(dst, src);
                }
                cp_commit(); cp_wait0();
            }
            __syncthreads();

            for (int kt = 0; kt < 8; kt++) {
                const int cur = kt & 1;
                if (kt < 7) {
                    const int q0 = tid * 2;
                    #pragma unroll
                    for (int q = q0; q < q0 + 2; q++) {
                        int r = q >> 5, c = (q & 31) * 4;
                        const float* src = W2 + (size_t)(kh*KH + (kt+1)*KT + r) * 1024 + n0 + c;
                        unsigned dst = (unsigned)__cvta_generic_to_shared(
                            &w2s[(cur^1)*2048 + r*TNW + c]);
                        cp16(dst, src);
                    }
                    cp_commit();
                }
                const float* hsb = hs + (kt * KT) * TE + ty * 8;
                const float* wsb = w2s + cur * 2048 + tx * 8;
                #pragma unroll
                for (int kk = 0; kk < KT; kk++) {
                    float4 a0 = *(const float4*)(hsb + kk * TE);
                    float4 a1 = *(const float4*)(hsb + kk * TE + 4);
                    u64 a2[8] = { pack2s(a0.x), pack2s(a0.y), pack2s(a0.z), pack2s(a0.w),
                                  pack2s(a1.x), pack2s(a1.y), pack2s(a1.z), pack2s(a1.w) };
                    const u64* br = (const u64*)(wsb + kk * TNW);
                    u64 b0v = br[0], b1v = br[1], b2v = br[2], b3v = br[3];
                    #pragma unroll
                    for (int i = 0; i < 8; i++) {
                        fma2(acc[i][0], a2[i], b0v);
                        fma2(acc[i][1], a2[i], b1v);
                        fma2(acc[i][2], a2[i], b2v);
                        fma2(acc[i][3], a2[i], b3v);
                    }
                }
                cp_wait0();
                __syncthreads();
            }

            // fold: w columns of this chunk have fixed block b, i = i0 + tx/2, j in 8-half
            const int bblk = chunk >> 1;
            const int i = ((chunk & 1) << 3) + (tx >> 1);
            const int j0 = (tx & 1) << 3;
            const int m = tx >> 1;   // stagger edges to decollide smem atomics
            #pragma unroll
            for (int rr = 0; rr < 8; rr++) {
                int r = (rr + m) & 7;
                int e = ty * 8 + r;
                float w[8];
                #pragma unroll
                for (int q = 0; q < 4; q++) {
                    float2 t = unp2(acc[r][q]); w[q*2] = t.x; w[q*2+1] = t.y;
                }
                if (kh == 0) {
                    #pragma unroll
                    for (int u = 0; u < 8; u++) w[u] += b2s[n0 + tx*8 + u];
                }
                if (bblk == 0) {
                    float L = Lss[e*16 + i];
                    #pragma unroll
                    for (int u = 0; u < 8; u++) atomicAdd(&osum[e*16 + j0 + u], L * w[u]);
                } else if (bblk == 1) {
                    float L = Lvv[e*16 + i];
                    #pragma unroll
                    for (int u = 0; u < 8; u++) atomicAdd(&osum[e*16 + j0 + u], L * w[u]);
                } else if (bblk == 2) {
                    float L = Lsv[e*16 + i];
                    #pragma unroll
                    for (int u = 0; u < 8; u++) atomicAdd(&tsvs[e*16 + j0 + u], L * w[u]);
                } else {
                    float L0 = Lvs[e*48 + i*3], L1 = Lvs[e*48 + i*3 + 1], L2 = Lvs[e*48 + i*3 + 2];
                    #pragma unroll
                    for (int u = 0; u < 8; u++) {
                        int jb = e*48 + (j0 + u)*3;
                        atomicAdd(&rvss[jb],     L0 * w[u]);
                        atomicAdd(&rvss[jb + 1], L1 * w[u]);
                        atomicAdd(&rvss[jb + 2], L2 * w[u]);
                    }
                }
            }
        }
    }
    __syncthreads();

    // ---- stage 4: finalize and scatter to nodes ----
    {
        const int eg = eb + el;
        if (eg < E) {
            const float cS = 0.17677669529663688110f;  // sqrt(1/32) = c_s = c_v/sqrt(3)
            const float sc = cS * scale_out;
            int dst = edst[eg];
            float* ob = out + (size_t)dst * 64;
            if (pp == 0) {
                #pragma unroll
                for (int c = 0; c < 16; c++)
                    atomicAdd(&ob[c], sc * osum[el*16 + c]);
                #pragma unroll
                for (int c = 16; c < 32; c++) {
                    int t = c - 16; int j = t / 3, a = t - j*3;
                    float val = tsvs[el*16 + j] * y1s[el*4 + a] + rvss[el*48 + j*3 + a];
                    atomicAdd(&ob[c], sc * val);
                }
            } else {
                #pragma unroll
                for (int c = 32; c < 64; c++) {
                    int t = c - 16; int j = t / 3, a = t - j*3;
                    float val = tsvs[el*16 + j] * y1s[el*4 + a] + rvss[el*48 + j*3 + a];
                    atomicAdd(&ob[c], sc * val);
                }
            }
        }
    }
}

extern "C" void kernel_launch(void* const* d_in, const int* in_sizes, int n_in,
                              void* d_out, int out_size) {
    const float* nodef = (const float*)d_in[0];
    const float* eattr = (const float*)d_in[1];
    const float* eemb  = (const float*)d_in[2];
    const float* W1    = (const float*)d_in[3];
    const float* b1    = (const float*)d_in[4];
    const float* W2    = (const float*)d_in[5];
    const float* b2    = (const float*)d_in[6];
    const int*   esrc  = (const int*)d_in[7];
    const int*   edst  = (const int*)d_in[8];
    float* out = (float*)d_out;

    int E  = in_sizes[7];
    int Nn = out_size / 64;
    float scale_out = 1.0f / sqrtf((float)E / (float)Nn);

    cudaMemsetAsync(d_out, 0, (size_t)out_size * sizeof(float));

    const int SMEM_BYTES = SMEM_FLOATS * 4;
    cudaFuncSetAttribute(nequip_fused, cudaFuncAttributeMaxDynamicSharedMemorySize, SMEM_BYTES);

    int grid = (E + TE - 1) / TE;
    nequip_fused<<<grid, 256, SMEM_BYTES>>>(nodef, eattr, eemb, W1, b1, W2, b2,
                                            esrc, edst, out, E, scale_out);
}

// round 2
// speedup vs baseline: 1.3041x; 1.3041x over previous
#include <cuda_runtime.h>
#include <math.h>

#define TE   128   // edges per block
#define HIDD 256
#define EMBD 18
#define KT   64    // k rows per pipeline step
#define NSTEP 16   // steps per kh-half: 8 chunks * 2

typedef unsigned long long u64;

__device__ __forceinline__ u64 pack2s(float x) {
    u64 r; asm("mov.b64 %0, {%1, %1};" : "=l"(r) : "f"(x)); return r;
}
__device__ __forceinline__ void fma2(u64& d, u64 a, u64 b) {
    asm("fma.rn.f32x2 %0, %1, %2, %0;" : "+l"(d) : "l"(a), "l"(b));
}
__device__ __forceinline__ float2 unp2(u64 v) {
    float2 r; asm("mov.b64 {%0, %1}, %2;" : "=f"(r.x), "=f"(r.y) : "l"(v)); return r;
}
__device__ __forceinline__ void cp16(unsigned dst, const void* src) {
    asm volatile("cp.async.cg.shared.global [%0], [%1], 16;" :: "r"(dst), "l"(src));
}
__device__ __forceinline__ void cp_commit() { asm volatile("cp.async.commit_group;"); }
template<int N> __device__ __forceinline__ void cp_wait() {
    asm volatile("cp.async.wait_group %0;" :: "n"(N));
}

// Shared memory layout (float offsets):
//  hs    [128][128]     0      (16384)
//  w2buf [2][64][128]   16384  (16384)  aliases: embs@16384(2304) W1s@18688(2304) b1s@20992(128)
//  Lss   [128][16]      32768  (2048)
//  Lvv   [128][16]      34816  (2048)
//  Lsv   [128][16]      36864  (2048)
//  Lvs   [128][16][3]   38912  (6144)
//  y1s   [128][4]       45056  (512)
//  osum  [128][16]      45568  (2048)  } contiguous 10240-float accumulator region
//  tsvs  [128][16]      47616  (2048)  }
//  rvss  [128][16][3]   49664  (6144)  }
#define OFF_HS    0
#define OFF_W2    16384
#define OFF_EMB   16384
#define OFF_W1    18688
#define OFF_B1    20992
#define OFF_LSS   32768
#define OFF_LVV   34816
#define OFF_LSV   36864
#define OFF_LVS   38912
#define OFF_Y1    45056
#define OFF_OSUM  45568
#define OFF_TSV   47616
#define OFF_RVS   49664
#define SMEM_FLOATS 55808

__global__ __launch_bounds__(512, 1)
void nequip_fused(const float* __restrict__ nodef,
                  const float* __restrict__ eattr,
                  const float* __restrict__ eemb,
                  const float* __restrict__ W1,
                  const float* __restrict__ b1,
                  const float* __restrict__ W2,
                  const float* __restrict__ b2,
                  const int* __restrict__ esrc,
                  const int* __restrict__ edst,
                  float* __restrict__ out,
                  int E, float scale_out)
{
    extern __shared__ float sm[];
    const int tid = threadIdx.x;
    const int tx = tid & 15, ty = tid >> 4;     // GEMM map: n=tx*8, e=ty*4
    const int el = tid & 127, pp = tid >> 7;    // per-edge map: 4 groups
    const int eb = blockIdx.x * TE;

    // ---- stage 0: zero the contiguous accumulator region ----
    #pragma unroll
    for (int i = tid; i < 10240; i += 512) sm[OFF_OSUM + i] = 0.f;

    // ---- stage 2: per-edge left vectors (each pp group handles 4 i's) ----
    {
        const int eg = eb + el;
        if (eg < E) {
            const float inv3 = 0.57735026918962576451f;  // 1/sqrt(3)
            int src = esrc[eg];
            const float* x = nodef + (size_t)src * 64;
            float4 ya = *(const float4*)(eattr + (size_t)eg * 4);
            if (pp == 0) {
                sm[OFF_Y1 + el*4 + 0] = ya.y;
                sm[OFF_Y1 + el*4 + 1] = ya.z;
                sm[OFF_Y1 + el*4 + 2] = ya.w;
            }
            float4 sv = *(const float4*)(x + pp * 4);
            float s4[4] = {sv.x, sv.y, sv.z, sv.w};
            float vv[12];
            const float4* vx = (const float4*)(x + 16 + pp * 12);
            #pragma unroll
            for (int q = 0; q < 3; q++) {
                float4 t = vx[q];
                vv[q*4] = t.x; vv[q*4+1] = t.y; vv[q*4+2] = t.z; vv[q*4+3] = t.w;
            }
            #pragma unroll
            for (int il = 0; il < 4; il++) {
                int i = pp * 4 + il;
                sm[OFF_LSS + el*16 + i] = ya.x * s4[il];
                sm[OFF_LSV + el*16 + i] = s4[il];
                sm[OFF_LVV + el*16 + i] =
                    inv3 * (ya.y*vv[il*3] + ya.z*vv[il*3+1] + ya.w*vv[il*3+2]);
                sm[OFF_LVS + el*48 + i*3 + 0] = ya.x * vv[il*3 + 0];
                sm[OFF_LVS + el*48 + i*3 + 1] = ya.x * vv[il*3 + 1];
                sm[OFF_LVS + el*48 + i*3 + 2] = ya.x * vv[il*3 + 2];
            }
        }
    }

    for (int kh = 0; kh < 2; kh++) {
        __syncthreads();  // w2buf region free; stage0/2 writes visible (kh=0)

        // ---- stage the emb / W1-half / b1-half (aliased into w2buf) ----
        for (int i = tid; i < TE * EMBD; i += 512) {
            int g = eb * EMBD + i;
            sm[OFF_EMB + i] = (g < E * EMBD) ? eemb[g] : 0.f;
        }
        for (int i = tid; i < EMBD * 128; i += 512)
            sm[OFF_W1 + i] = W1[(i >> 7) * HIDD + kh * 128 + (i & 127)];
        if (tid < 128) sm[OFF_B1 + tid] = b1[kh * 128 + tid];
        __syncthreads();

        // ---- stage 1: h = silu(emb @ W1 + b1), transposed hs[c][e] ----
        {
            float er[EMBD];
            #pragma unroll
            for (int t = 0; t < EMBD; t++) er[t] = sm[OFF_EMB + el * EMBD + t];
            const int c0 = pp * 32;
            #pragma unroll 4
            for (int cl = 0; cl < 32; cl++) {
                int c = c0 + cl;
                float acc = sm[OFF_B1 + c];
                #pragma unroll
                for (int t = 0; t < EMBD; t++)
                    acc = fmaf(er[t], sm[OFF_W1 + t*128 + c], acc);
                float sg = 1.f / (1.f + __expf(-acc));
                sm[OFF_HS + c * TE + el] = acc * sg;
            }
        }
        __syncthreads();  // hs ready; emb/W1 region free for W2 tiles

        // ---- preload step 0 ----
        {
            #pragma unroll
            for (int jj = 0; jj < 4; jj++) {
                int q = tid + 512 * jj;
                int r = q >> 5, c = (q & 31) * 4;
                const float* src = W2 + (size_t)(kh*128 + r) * 1024 + c;
                cp16((unsigned)__cvta_generic_to_shared(&sm[OFF_W2 + r*128 + c]), src);
            }
            cp_commit();
        }

        u64 acc[4][4];
        for (int s = 0; s < NSTEP; s++) {
            const int buf = s & 1;
            if ((s & 1) == 0) {
                #pragma unroll
                for (int r = 0; r < 4; r++)
                    #pragma unroll
                    for (int q = 0; q < 4; q++) acc[r][q] = 0ull;
            }
            __syncthreads();  // readers of buf^1 (step s-1) done
            if (s + 1 < NSTEP) {
                const int chunk1 = (s + 1) >> 1, half1 = (s + 1) & 1;
                #pragma unroll
                for (int jj = 0; jj < 4; jj++) {
                    int q = tid + 512 * jj;
                    int r = q >> 5, c = (q & 31) * 4;
                    const float* src =
                        W2 + (size_t)(kh*128 + half1*KT + r) * 1024 + chunk1*128 + c;
                    cp16((unsigned)__cvta_generic_to_shared(
                             &sm[OFF_W2 + (buf^1)*8192 + r*128 + c]), src);
                }
                cp_commit();
                cp_wait<1>();   // load s complete (s+1 may be in flight)
            } else {
                cp_wait<0>();
            }
            __syncthreads();    // buf data visible to all

            // ---- compute 64 kk on buf ----
            const float* hsb = sm + OFF_HS + ((s & 1) * KT) * TE + ty * 4;
            const float* wsb = sm + OFF_W2 + buf * 8192 + tx * 8;
            #pragma unroll 8
            for (int kk = 0; kk < KT; kk++) {
                float4 a0 = *(const float4*)(hsb + kk * TE);
                u64 a2[4] = { pack2s(a0.x), pack2s(a0.y), pack2s(a0.z), pack2s(a0.w) };
                const u64* br = (const u64*)(wsb + kk * 128);
                u64 b0v = br[0], b1v = br[1], b2v = br[2], b3v = br[3];
                #pragma unroll
                for (int r = 0; r < 4; r++) {
                    fma2(acc[r][0], a2[r], b0v);
                    fma2(acc[r][1], a2[r], b1v);
                    fma2(acc[r][2], a2[r], b2v);
                    fma2(acc[r][3], a2[r], b3v);
                }
            }

            if (s & 1) {
                // ---- fold chunk (s>>1): shuffle-reduce over i, plain smem RMW ----
                const int chunkI = s >> 1;
                const int bblk = chunkI >> 1;
                const int i = ((chunkI & 1) << 3) + (tx >> 1);
                const int j0 = (tx & 1) << 3;
                #pragma unroll
                for (int r = 0; r < 4; r++) {
                    const int e = ty * 4 + r;
                    float w[8];
                    #pragma unroll
                    for (int q = 0; q < 4; q++) {
                        float2 t = unp2(acc[r][q]); w[q*2] = t.x; w[q*2+1] = t.y;
                    }
                    if (kh == 0) {
                        const float* bp = b2 + chunkI * 128 + tx * 8;
                        #pragma unroll
                        for (int u = 0; u < 8; u++) w[u] += __ldg(bp + u);
                    }
                    if (bblk < 2) {
                        float L = sm[(bblk == 0 ? OFF_LSS : OFF_LVV) + e*16 + i];
                        float v[8];
                        #pragma unroll
                        for (int u = 0; u < 8; u++) v[u] = L * w[u];
                        #pragma unroll
                        for (int m = 2; m <= 8; m <<= 1)
                            #pragma unroll
                            for (int u = 0; u < 8; u++)
                                v[u] += __shfl_xor_sync(0xffffffffu, v[u], m);
                        if (tx < 2) {
                            #pragma unroll
                            for (int u = 0; u < 8; u++)
                                sm[OFF_OSUM + e*16 + j0 + u] += v[u];
                        }
                    } else if (bblk == 2) {
                        float L = sm[OFF_LSV + e*16 + i];
                        float v[8];
                        #pragma unroll
                        for (int u = 0; u < 8; u++) v[u] = L * w[u];
                        #pragma unroll
                        for (int m = 2; m <= 8; m <<= 1)
                            #pragma unroll
                            for (int u = 0; u < 8; u++)
                                v[u] += __shfl_xor_sync(0xffffffffu, v[u], m);
                        if (tx < 2) {
                            #pragma unroll
                            for (int u = 0; u < 8; u++)
                                sm[OFF_TSV + e*16 + j0 + u] += v[u];
                        }
                    } else {
                        float L0 = sm[OFF_LVS + e*48 + i*3 + 0];
                        float L1 = sm[OFF_LVS + e*48 + i*3 + 1];
                        float L2 = sm[OFF_LVS + e*48 + i*3 + 2];
                        float v0[8], v1[8], v2[8];
                        #pragma unroll
                        for (int u = 0; u < 8; u++) {
                            v0[u] = L0 * w[u]; v1[u] = L1 * w[u]; v2[u] = L2 * w[u];
                        }
                        #pragma unroll
                        for (int m = 2; m <= 8; m <<= 1)
                            #pragma unroll
                            for (int u = 0; u < 8; u++) {
                                v0[u] += __shfl_xor_sync(0xffffffffu, v0[u], m);
                                v1[u] += __shfl_xor_sync(0xffffffffu, v1[u], m);
                                v2[u] += __shfl_xor_sync(0xffffffffu, v2[u], m);
                            }
                        if (tx < 2) {
                            #pragma unroll
                            for (int u = 0; u < 8; u++) {
                                int jb = OFF_RVS + e*48 + (j0 + u)*3;
                                sm[jb + 0] += v0[u];
                                sm[jb + 1] += v1[u];
                                sm[jb + 2] += v2[u];
                            }
                        }
                    }
                }
            }
        }
    }
    __syncthreads();

    // ---- stage 4: finalize and scatter to nodes ----
    {
        const int eg = eb + el;
        if (eg < E) {
            const float cS = 0.17677669529663688110f;  // sqrt(1/32)
            const float scl = cS * scale_out;
            int dst = edst[eg];
            float* ob = out + (size_t)dst * 64;
            if (pp == 0) {
                #pragma unroll
                for (int c = 0; c < 16; c++)
                    atomicAdd(&ob[c], scl * sm[OFF_OSUM + el*16 + c]);
            } else {
                const int base = (pp - 1) * 16;
                #pragma unroll
                for (int cc = 0; cc < 16; cc++) {
                    int t = base + cc;         // 0..47
                    int j = t / 3, a = t - j * 3;
                    float val = sm[OFF_TSV + el*16 + j] * sm[OFF_Y1 + el*4 + a]
                              + sm[OFF_RVS + el*48 + j*3 + a];
                    atomicAdd(&ob[16 + t], scl * val);
                }
            }
        }
    }
}

extern "C" void kernel_launch(void* const* d_in, const int* in_sizes, int n_in,
                              void* d_out, int out_size) {
    const float* nodef = (const float*)d_in[0];
    const float* eattr = (const float*)d_in[1];
    const float* eemb  = (const float*)d_in[2];
    const float* W1    = (const float*)d_in[3];
    const float* b1    = (const float*)d_in[4];
    const float* W2    = (const float*)d_in[5];
    const float* b2    = (const float*)d_in[6];
    const int*   esrc  = (const int*)d_in[7];
    const int*   edst  = (const int*)d_in[8];
    float* out = (float*)d_out;

    int E  = in_sizes[7];
    int Nn = out_size / 64;
    float scale_out = 1.0f / sqrtf((float)E / (float)Nn);

    cudaMemsetAsync(d_out, 0, (size_t)out_size * sizeof(float));

    const int SMEM_BYTES = SMEM_FLOATS * 4;
    cudaFuncSetAttribute(nequip_fused, cudaFuncAttributeMaxDynamicSharedMemorySize, SMEM_BYTES);

    int grid = (E + TE - 1) / TE;
    nequip_fused<<<grid, 512, SMEM_BYTES>>>(nodef, eattr, eemb, W1, b1, W2, b2,
                                            esrc, edst, out, E, scale_out);
}

// round 5
// speedup vs baseline: 4.0495x; 3.1052x over previous
#include <cuda_runtime.h>
#include <cuda_bf16.h>
#include <math.h>

typedef unsigned u32;
typedef unsigned long long u64;

#define TE 128

// Pre-split, pre-swizzled W2 tile images: [split][ktile][chunk][128n x 128k bf16 = 32KB]
__device__ __align__(16) __nv_bfloat16 g_B[2][2][8][16384];

// ---------------- helpers ----------------
__device__ __forceinline__ u32 smem_u32(const void* p) {
    u32 a; asm("{ .reg .u64 t; cvta.to.shared.u64 t, %1; cvt.u32.u64 %0, t; }" : "=r"(a) : "l"(p));
    return a;
}
__device__ __forceinline__ void cp16(u32 dst, const void* src) {
    asm volatile("cp.async.cg.shared.global [%0], [%1], 16;" :: "r"(dst), "l"(src));
}
__device__ __forceinline__ void cp_commit() { asm volatile("cp.async.commit_group;"); }
template<int N> __device__ __forceinline__ void cp_wait() {
    asm volatile("cp.async.wait_group %0;" :: "n"(N));
}
__device__ __forceinline__ void ldsm4(u32* r, u32 addr) {
    asm volatile("ldmatrix.sync.aligned.m8n8.x4.shared.b16 {%0,%1,%2,%3}, [%4];"
        : "=r"(r[0]), "=r"(r[1]), "=r"(r[2]), "=r"(r[3]) : "r"(addr));
}
__device__ __forceinline__ void mma16816(float* d, const u32* a, u32 b0, u32 b1) {
    asm volatile("mma.sync.aligned.m16n8k16.row.col.f32.bf16.bf16.f32 "
        "{%0,%1,%2,%3}, {%4,%5,%6,%7}, {%8,%9}, {%0,%1,%2,%3};"
        : "+f"(d[0]), "+f"(d[1]), "+f"(d[2]), "+f"(d[3])
        : "r"(a[0]), "r"(a[1]), "r"(a[2]), "r"(a[3]), "r"(b0), "r"(b1));
}

// ---------------- smem layout ----------------
// bytes:
#define RING_B 0          // 2 stages x 32768
#define HS_B   65536      // 2 splits x 32768 (A tiles, current k-half)
// float offsets (from smem base):
#define W1S_F  32768      // [18][256]
#define B1S_F  37376      // 256
#define B2S_F  37632      // 1024
#define EMBS_F 38656      // 128*18
#define LSS_F  40960      // 128*16
#define LVV_F  43008
#define LSV_F  45056
#define LVS_F  47104      // 128*48
#define Y1_F   53248      // 128*4
#define SMEM_BYTES 215040

// ---------------- prep: split + swizzle W2 ----------------
__global__ void prep_w2(const float* __restrict__ W2) {
    int idx = blockIdx.x * blockDim.x + threadIdx.x;
    if (idx >= 256 * 1024) return;
    int k = idx >> 10, n = idx & 1023;
    float v = W2[idx];
    __nv_bfloat16 hi = __float2bfloat16(v);
    __nv_bfloat16 lo = __float2bfloat16(v - __bfloat162float(hi));
    int kt = k >> 7, kl = k & 127, chunk = n >> 7, nl = n & 127;
    int off = nl * 256 + (((kl >> 3) ^ (nl & 7)) << 4) + (kl & 7) * 2;  // bytes
    g_B[0][kt][chunk][off >> 1] = hi;
    g_B[1][kt][chunk][off >> 1] = lo;
}

// ---------------- h compute (one k-half) ----------------
__device__ __forceinline__ void compute_h(float* smf, char* smem, int tid, int kh) {
    const int e = tid & 127;
    const int ch = tid >> 7;           // column half (64 cols each)
    float er[18];
    #pragma unroll
    for (int t = 0; t < 18; t++) er[t] = smf[EMBS_F + e * 18 + t];
    const int cbase = ch * 64;
    #pragma unroll 2
    for (int cc = 0; cc < 64; cc += 2) {
        const int c = cbase + cc;              // local k in [0,128)
        float h[2];
        #pragma unroll
        for (int u = 0; u < 2; u++) {
            float a = smf[B1S_F + kh * 128 + c + u];
            #pragma unroll
            for (int t = 0; t < 18; t++)
                a = fmaf(er[t], smf[W1S_F + t * 256 + kh * 128 + c + u], a);
            h[u] = a / (1.f + __expf(-a));
        }
        __nv_bfloat16 h0 = __float2bfloat16(h[0]);
        __nv_bfloat16 h1 = __float2bfloat16(h[1]);
        __nv_bfloat16 l0 = __float2bfloat16(h[0] - __bfloat162float(h0));
        __nv_bfloat16 l1 = __float2bfloat16(h[1] - __bfloat162float(h1));
        __nv_bfloat162 hp; hp.x = h0; hp.y = h1;
        __nv_bfloat162 lp; lp.x = l0; lp.y = l1;
        u32 off = (u32)(e * 256 + (((c >> 3) ^ (e & 7)) << 4) + (c & 7) * 2);
        *(u32*)(smem + HS_B + off)         = *(u32*)&hp;
        *(u32*)(smem + HS_B + 32768 + off) = *(u32*)&lp;
    }
}

// ---------------- main kernel ----------------
__global__ __launch_bounds__(256, 1)
void nequip_mma(const float* __restrict__ nodef,
                const float* __restrict__ eattr,
                const float* __restrict__ eemb,
                const float* __restrict__ W1,
                const float* __restrict__ bias1,
                const float* __restrict__ b2,
                const int* __restrict__ esrc,
                const int* __restrict__ edst,
                float* __restrict__ out,
                int E, float scl)
{
    extern __shared__ char smem[];
    float* smf = (float*)smem;
    const u32 sb = smem_u32(smem);
    const int tid = threadIdx.x;
    const int wid = tid >> 5, lane = tid & 31;
    const int wgtid = tid & 127, wg = tid >> 7;
    const int eb = blockIdx.x * TE;

    // ---- stage constants ----
    for (int i = tid; i < 18 * 256; i += 256) smf[W1S_F + i] = W1[i];
    smf[B1S_F + tid] = bias1[tid];
    for (int i = tid; i < 1024; i += 256) smf[B2S_F + i] = b2[i];
    for (int i = tid; i < 128 * 18; i += 256) {
        int g = eb * 18 + i;
        smf[EMBS_F + i] = (g < E * 18) ? eemb[g] : 0.f;
    }

    // ---- per-edge left vectors ----
    {
        const int eg = eb + wgtid;
        if (eg < E) {
            const float inv3 = 0.57735026918962576451f;
            int src = esrc[eg];
            const float* x = nodef + (size_t)src * 64;
            float4 ya = *(const float4*)(eattr + (size_t)eg * 4);
            if (wg == 0) {
                smf[Y1_F + wgtid*4 + 0] = ya.y;
                smf[Y1_F + wgtid*4 + 1] = ya.z;
                smf[Y1_F + wgtid*4 + 2] = ya.w;
            }
            float4 s0 = *(const float4*)(x + wg*8);
            float4 s1 = *(const float4*)(x + wg*8 + 4);
            float sv[8] = {s0.x,s0.y,s0.z,s0.w,s1.x,s1.y,s1.z,s1.w};
            float vv[24];
            const float4* vx = (const float4*)(x + 16 + wg*24);
            #pragma unroll
            for (int q = 0; q < 6; q++) {
                float4 t = vx[q];
                vv[q*4] = t.x; vv[q*4+1] = t.y; vv[q*4+2] = t.z; vv[q*4+3] = t.w;
            }
            #pragma unroll
            for (int il = 0; il < 8; il++) {
                int i = wg*8 + il;
                smf[LSS_F + wgtid*16 + i] = ya.x * sv[il];
                smf[LSV_F + wgtid*16 + i] = sv[il];
                smf[LVV_F + wgtid*16 + i] =
                    inv3 * (ya.y*vv[il*3] + ya.z*vv[il*3+1] + ya.w*vv[il*3+2]);
                smf[LVS_F + wgtid*48 + i*3 + 0] = ya.x * vv[il*3 + 0];
                smf[LVS_F + wgtid*48 + i*3 + 1] = ya.x * vv[il*3 + 1];
                smf[LVS_F + wgtid*48 + i*3 + 2] = ya.x * vv[il*3 + 2];
            }
        }
    }

    // ---- prologue: issue B tile 0 (kh0, chunk0, split0) ----
    {
        const char* src = (const char*)&g_B[0][0][0][0];
        #pragma unroll
        for (int jj = 0; jj < 8; jj++) {
            int seg = tid + 256 * jj;
            cp16(sb + RING_B + seg * 16, src + seg * 16);
        }
        cp_commit();
    }
    __syncthreads();        // staged smem visible
    compute_h(smf, smem, tid, 0);

    // ---- per-lane state ----
    const int m0 = wid * 16;
    const u32 aRow = (u32)(m0 + (lane & 15));
    const u32 aK   = (u32)(lane >> 4);           // +0/+1 k-unit
    const u32 aX   = aRow & 7;
    const u32 aAddr0 = sb + HS_B + aRow * 256;   // + split*32768 + u*16
    const u32 bRow = (u32)(((lane >> 4) << 3) + (lane & 7));
    const u32 bK   = (u32)((lane >> 3) & 1);
    const u32 bX   = bRow & 7;

    float acc[16][4];
    float osum[2][4], tsv[2][4], rvs[2][4][3];
    #pragma unroll
    for (int eh = 0; eh < 2; eh++)
        #pragma unroll
        for (int q = 0; q < 4; q++) {
            osum[eh][q] = 0.f; tsv[eh][q] = 0.f;
            rvs[eh][q][0] = 0.f; rvs[eh][q][1] = 0.f; rvs[eh][q][2] = 0.f;
        }

    // ---- main pipeline: 32 tiles = 2 kh x 8 chunk x 2 split ----
    for (int t = 0; t < 32; t++) {
        cp_wait<0>();
        __syncthreads();                 // tile t visible; tile t-1 readers done
        if (t == 16) {                   // rewrite A for k-half 1
            compute_h(smf, smem, tid, 1);
            __syncthreads();
        }
        if (t + 1 < 32) {
            const int t1 = t + 1;
            const int sp1 = t1 & 1, ch1 = (t1 >> 1) & 7, kh1 = t1 >> 4;
            const char* src = (const char*)&g_B[sp1][kh1][ch1][0];
            const u32 dst = sb + RING_B + ((u32)(t1 & 1)) * 32768;
            #pragma unroll
            for (int jj = 0; jj < 8; jj++) {
                int seg = tid + 256 * jj;
                cp16(dst + seg * 16, src + seg * 16);
            }
            cp_commit();
        }

        const int split = t & 1;
        const u32 ring = sb + RING_B + ((u32)(t & 1)) * 32768;

        if (split == 0) {
            #pragma unroll
            for (int nt = 0; nt < 16; nt++)
                #pragma unroll
                for (int q = 0; q < 4; q++) acc[nt][q] = 0.f;
        }

        #pragma unroll 2
        for (int ks = 0; ks < 8; ks++) {
            u32 a0[4], a1[4];
            {
                u32 u = ((u32)(ks * 2) + aK) ^ aX;
                u32 addr = aAddr0 + (u << 4);
                ldsm4(a0, addr);                       // A0 (hi split)
                if (split == 0) ldsm4(a1, addr + 32768); // A1 (lo split)
            }
            u32 bu = ((u32)(ks * 2) + bK) ^ bX;
            u32 bBase = ring + bRow * 256 + (bu << 4);
            #pragma unroll
            for (int p = 0; p < 8; p++) {
                u32 b[4];
                ldsm4(b, bBase + (u32)p * 4096);
                mma16816(acc[2*p],     a0, b[0], b[1]);
                mma16816(acc[2*p + 1], a0, b[2], b[3]);
                if (split == 0) {
                    mma16816(acc[2*p],     a1, b[0], b[1]);
                    mma16816(acc[2*p + 1], a1, b[2], b[3]);
                }
            }
        }

        if (split == 1) {
            // ---- fold chunk into register finals (lane-local, no atomics) ----
            const int chunk = (t >> 1) & 7;
            const int kh = t >> 4;
            const int bsel = chunk >> 1;
            const int ibase = (chunk & 1) << 3;
            const int e0 = m0 + (lane >> 2);
            #pragma unroll
            for (int nt = 0; nt < 16; nt++) {
                const int i = ibase + (nt >> 1);
                const int qb = (nt & 1) << 1;
                float b2v0 = 0.f, b2v1 = 0.f;
                if (kh == 0) {
                    const int nb = chunk * 128 + nt * 8 + (lane & 3) * 2;
                    b2v0 = smf[B2S_F + nb];
                    b2v1 = smf[B2S_F + nb + 1];
                }
                #pragma unroll
                for (int eh = 0; eh < 2; eh++) {
                    const int e = e0 + eh * 8;
                    const float w0 = acc[nt][eh*2 + 0] + b2v0;
                    const float w1 = acc[nt][eh*2 + 1] + b2v1;
                    if (bsel == 0) {
                        float L = smf[LSS_F + e*16 + i];
                        osum[eh][qb]   += L * w0;
                        osum[eh][qb+1] += L * w1;
                    } else if (bsel == 1) {
                        float L = smf[LVV_F + e*16 + i];
                        osum[eh][qb]   += L * w0;
                        osum[eh][qb+1] += L * w1;
                    } else if (bsel == 2) {
                        float L = smf[LSV_F + e*16 + i];
                        tsv[eh][qb]   += L * w0;
                        tsv[eh][qb+1] += L * w1;
                    } else {
                        float L0 = smf[LVS_F + e*48 + i*3 + 0];
                        float L1 = smf[LVS_F + e*48 + i*3 + 1];
                        float L2 = smf[LVS_F + e*48 + i*3 + 2];
                        rvs[eh][qb][0]   += L0 * w0;
                        rvs[eh][qb][1]   += L1 * w0;
                        rvs[eh][qb][2]   += L2 * w0;
                        rvs[eh][qb+1][0] += L0 * w1;
                        rvs[eh][qb+1][1] += L1 * w1;
                        rvs[eh][qb+1][2] += L2 * w1;
                    }
                }
            }
        }
    }

    // ---- final combine + scatter (from registers) ----
    #pragma unroll
    for (int eh = 0; eh < 2; eh++) {
        const int e = m0 + (lane >> 2) + eh * 8;
        const int eg = eb + e;
        if (eg < E) {
            const int dst = edst[eg];
            float* ob = out + (size_t)dst * 64;
            const float y1a = smf[Y1_F + e*4 + 0];
            const float y1b = smf[Y1_F + e*4 + 1];
            const float y1c = smf[Y1_F + e*4 + 2];
            #pragma unroll
            for (int q = 0; q < 4; q++) {
                const int j = ((q >> 1) << 3) + (lane & 3) * 2 + (q & 1);
                atomicAdd(&ob[j], scl * osum[eh][q]);
                atomicAdd(&ob[16 + j*3 + 0], scl * (tsv[eh][q] * y1a + rvs[eh][q][0]));
                atomicAdd(&ob[16 + j*3 + 1], scl * (tsv[eh][q] * y1b + rvs[eh][q][1]));
                atomicAdd(&ob[16 + j*3 + 2], scl * (tsv[eh][q] * y1c + rvs[eh][q][2]));
            }
        }
    }
}

extern "C" void kernel_launch(void* const* d_in, const int* in_sizes, int n_in,
                              void* d_out, int out_size) {
    const float* nodef = (const float*)d_in[0];
    const float* eattr = (const float*)d_in[1];
    const float* eemb  = (const float*)d_in[2];
    const float* W1    = (const float*)d_in[3];
    const float* b1    = (const float*)d_in[4];
    const float* W2    = (const float*)d_in[5];
    const float* b2    = (const float*)d_in[6];
    const int*   esrc  = (const int*)d_in[7];
    const int*   edst  = (const int*)d_in[8];
    float* out = (float*)d_out;

    int E  = in_sizes[7];
    int Nn = out_size / 64;
    const float cS = 0.17677669529663688110f;  // sqrt(1/32)
    float scl = cS / sqrtf((float)E / (float)Nn);

    cudaMemsetAsync(d_out, 0, (size_t)out_size * sizeof(float));
    prep_w2<<<1024, 256>>>(W2);

    cudaFuncSetAttribute(nequip_mma, cudaFuncAttributeMaxDynamicSharedMemorySize, SMEM_BYTES);
    int grid = (E + TE - 1) / TE;
    nequip_mma<<<grid, 256, SMEM_BYTES>>>(nodef, eattr, eemb, W1, b1, b2,
                                          esrc, edst, out, E, scl);
}

// round 6
// speedup vs baseline: 4.0666x; 1.0042x over previous
#include <cuda_runtime.h>
#include <cuda_bf16.h>
#include <math.h>

typedef unsigned u32;
typedef unsigned long long u64;

#define TE 128

// Pre-split, pre-swizzled W2 tile images: [split][ktile][chunk][128n x 128k bf16 = 32KB]
__device__ __align__(16) __nv_bfloat16 g_B[2][2][8][16384];

// ---------------- helpers ----------------
__device__ __forceinline__ u32 smem_u32(const void* p) {
    u32 a; asm("{ .reg .u64 t; cvta.to.shared.u64 t, %1; cvt.u32.u64 %0, t; }" : "=r"(a) : "l"(p));
    return a;
}
__device__ __forceinline__ void cp16(u32 dst, const void* src) {
    asm volatile("cp.async.cg.shared.global [%0], [%1], 16;" :: "r"(dst), "l"(src));
}
__device__ __forceinline__ void cp_commit() { asm volatile("cp.async.commit_group;"); }
template<int N> __device__ __forceinline__ void cp_wait() {
    asm volatile("cp.async.wait_group %0;" :: "n"(N));
}
__device__ __forceinline__ void ldsm4(u32* r, u32 addr) {
    asm volatile("ldmatrix.sync.aligned.m8n8.x4.shared.b16 {%0,%1,%2,%3}, [%4];"
        : "=r"(r[0]), "=r"(r[1]), "=r"(r[2]), "=r"(r[3]) : "r"(addr));
}
__device__ __forceinline__ void mma16816(float* d, const u32* a, u32 b0, u32 b1) {
    asm volatile("mma.sync.aligned.m16n8k16.row.col.f32.bf16.bf16.f32 "
        "{%0,%1,%2,%3}, {%4,%5,%6,%7}, {%8,%9}, {%0,%1,%2,%3};"
        : "+f"(d[0]), "+f"(d[1]), "+f"(d[2]), "+f"(d[3])
        : "r"(a[0]), "r"(a[1]), "r"(a[2]), "r"(a[3]), "r"(b0), "r"(b1));
}

// ---------------- smem layout ----------------
// bytes:
#define RING_B 0          // 2 stages x 32768
#define HS_B   65536      // 2 splits x 32768 (A tiles, current k-half)
// float offsets (from smem base):
#define W1S_F  32768      // [18][256]
#define B1S_F  37376      // 256
#define B2S_F  37632      // 1024
#define EMBS_F 38656      // 128*18
#define LSS_F  40960      // 128*16
#define LVV_F  43008
#define LSV_F  45056
#define LVS_F  47104      // 128*48
#define Y1_F   53248      // 128*4
#define SMEM_BYTES 215040

// ---------------- prep: split + swizzle W2 ----------------
__global__ void prep_w2(const float* __restrict__ W2) {
    int idx = blockIdx.x * blockDim.x + threadIdx.x;
    if (idx >= 256 * 1024) return;
    int k = idx >> 10, n = idx & 1023;
    float v = W2[idx];
    __nv_bfloat16 hi = __float2bfloat16(v);
    __nv_bfloat16 lo = __float2bfloat16(v - __bfloat162float(hi));
    int kt = k >> 7, kl = k & 127, chunk = n >> 7, nl = n & 127;
    int off = nl * 256 + (((kl >> 3) ^ (nl & 7)) << 4) + (kl & 7) * 2;  // bytes
    g_B[0][kt][chunk][off >> 1] = hi;
    g_B[1][kt][chunk][off >> 1] = lo;
}

// ---------------- h compute (one k-half) ----------------
__device__ __forceinline__ void compute_h(float* smf, char* smem, int tid, int kh) {
    const int e = tid & 127;
    const int ch = tid >> 7;           // column half (64 cols each)
    float er[18];
    #pragma unroll
    for (int t = 0; t < 18; t++) er[t] = smf[EMBS_F + e * 18 + t];
    const int cbase = ch * 64;
    #pragma unroll 2
    for (int cc = 0; cc < 64; cc += 2) {
        const int c = cbase + cc;              // local k in [0,128)
        float h[2];
        #pragma unroll
        for (int u = 0; u < 2; u++) {
            float a = smf[B1S_F + kh * 128 + c + u];
            #pragma unroll
            for (int t = 0; t < 18; t++)
                a = fmaf(er[t], smf[W1S_F + t * 256 + kh * 128 + c + u], a);
            h[u] = a / (1.f + __expf(-a));
        }
        __nv_bfloat16 h0 = __float2bfloat16(h[0]);
        __nv_bfloat16 h1 = __float2bfloat16(h[1]);
        __nv_bfloat16 l0 = __float2bfloat16(h[0] - __bfloat162float(h0));
        __nv_bfloat16 l1 = __float2bfloat16(h[1] - __bfloat162float(h1));
        __nv_bfloat162 hp; hp.x = h0; hp.y = h1;
        __nv_bfloat162 lp; lp.x = l0; lp.y = l1;
        u32 off = (u32)(e * 256 + (((c >> 3) ^ (e & 7)) << 4) + (c & 7) * 2);
        *(u32*)(smem + HS_B + off)         = *(u32*)&hp;
        *(u32*)(smem + HS_B + 32768 + off) = *(u32*)&lp;
    }
}

// ---------------- main kernel ----------------
__global__ __launch_bounds__(256, 1)
void nequip_mma(const float* __restrict__ nodef,
                const float* __restrict__ eattr,
                const float* __restrict__ eemb,
                const float* __restrict__ W1,
                const float* __restrict__ bias1,
                const float* __restrict__ b2,
                const int* __restrict__ esrc,
                const int* __restrict__ edst,
                float* __restrict__ out,
                int E, float scl)
{
    extern __shared__ char smem[];
    float* smf = (float*)smem;
    const u32 sb = smem_u32(smem);
    const int tid = threadIdx.x;
    const int wid = tid >> 5, lane = tid & 31;
    const int wgtid = tid & 127, wg = tid >> 7;
    const int eb = blockIdx.x * TE;

    // ---- stage constants ----
    for (int i = tid; i < 18 * 256; i += 256) smf[W1S_F + i] = W1[i];
    smf[B1S_F + tid] = bias1[tid];
    for (int i = tid; i < 1024; i += 256) smf[B2S_F + i] = b2[i];
    for (int i = tid; i < 128 * 18; i += 256) {
        int g = eb * 18 + i;
        smf[EMBS_F + i] = (g < E * 18) ? eemb[g] : 0.f;
    }

    // ---- per-edge left vectors ----
    {
        const int eg = eb + wgtid;
        if (eg < E) {
            const float inv3 = 0.57735026918962576451f;
            int src = esrc[eg];
            const float* x = nodef + (size_t)src * 64;
            float4 ya = *(const float4*)(eattr + (size_t)eg * 4);
            if (wg == 0) {
                smf[Y1_F + wgtid*4 + 0] = ya.y;
                smf[Y1_F + wgtid*4 + 1] = ya.z;
                smf[Y1_F + wgtid*4 + 2] = ya.w;
            }
            float4 s0 = *(const float4*)(x + wg*8);
            float4 s1 = *(const float4*)(x + wg*8 + 4);
            float sv[8] = {s0.x,s0.y,s0.z,s0.w,s1.x,s1.y,s1.z,s1.w};
            float vv[24];
            const float4* vx = (const float4*)(x + 16 + wg*24);
            #pragma unroll
            for (int q = 0; q < 6; q++) {
                float4 t = vx[q];
                vv[q*4] = t.x; vv[q*4+1] = t.y; vv[q*4+2] = t.z; vv[q*4+3] = t.w;
            }
            #pragma unroll
            for (int il = 0; il < 8; il++) {
                int i = wg*8 + il;
                smf[LSS_F + wgtid*16 + i] = ya.x * sv[il];
                smf[LSV_F + wgtid*16 + i] = sv[il];
                smf[LVV_F + wgtid*16 + i] =
                    inv3 * (ya.y*vv[il*3] + ya.z*vv[il*3+1] + ya.w*vv[il*3+2]);
                smf[LVS_F + wgtid*48 + i*3 + 0] = ya.x * vv[il*3 + 0];
                smf[LVS_F + wgtid*48 + i*3 + 1] = ya.x * vv[il*3 + 1];
                smf[LVS_F + wgtid*48 + i*3 + 2] = ya.x * vv[il*3 + 2];
            }
        }
    }

    // ---- prologue: issue B tile 0 (kh0, chunk0, split0) ----
    {
        const char* src = (const char*)&g_B[0][0][0][0];
        #pragma unroll
        for (int jj = 0; jj < 8; jj++) {
            int seg = tid + 256 * jj;
            cp16(sb + RING_B + seg * 16, src + seg * 16);
        }
        cp_commit();
    }
    __syncthreads();        // staged smem visible
    compute_h(smf, smem, tid, 0);

    // ---- per-lane state ----
    const int m0 = wid * 16;
    const u32 aRow = (u32)(m0 + (lane & 15));
    const u32 aK   = (u32)(lane >> 4);           // +0/+1 k-unit
    const u32 aX   = aRow & 7;
    const u32 aAddr0 = sb + HS_B + aRow * 256;   // + split*32768 + u*16
    const u32 bRow = (u32)(((lane >> 4) << 3) + (lane & 7));
    const u32 bK   = (u32)((lane >> 3) & 1);
    const u32 bX   = bRow & 7;

    float acc[16][4];
    float osum[2][4], tsv[2][4], rvs[2][4][3];
    #pragma unroll
    for (int eh = 0; eh < 2; eh++)
        #pragma unroll
        for (int q = 0; q < 4; q++) {
            osum[eh][q] = 0.f; tsv[eh][q] = 0.f;
            rvs[eh][q][0] = 0.f; rvs[eh][q][1] = 0.f; rvs[eh][q][2] = 0.f;
        }

    // ---- main pipeline: 32 tiles = 2 kh x 8 chunk x 2 split ----
    for (int t = 0; t < 32; t++) {
        cp_wait<0>();
        __syncthreads();                 // tile t visible; tile t-1 readers done
        if (t == 16) {                   // rewrite A for k-half 1
            compute_h(smf, smem, tid, 1);
            __syncthreads();
        }
        if (t + 1 < 32) {
            const int t1 = t + 1;
            const int sp1 = t1 & 1, ch1 = (t1 >> 1) & 7, kh1 = t1 >> 4;
            const char* src = (const char*)&g_B[sp1][kh1][ch1][0];
            const u32 dst = sb + RING_B + ((u32)(t1 & 1)) * 32768;
            #pragma unroll
            for (int jj = 0; jj < 8; jj++) {
                int seg = tid + 256 * jj;
                cp16(dst + seg * 16, src + seg * 16);
            }
            cp_commit();
        }

        const int split = t & 1;
        const u32 ring = sb + RING_B + ((u32)(t & 1)) * 32768;

        if (split == 0) {
            #pragma unroll
            for (int nt = 0; nt < 16; nt++)
                #pragma unroll
                for (int q = 0; q < 4; q++) acc[nt][q] = 0.f;
        }

        #pragma unroll 2
        for (int ks = 0; ks < 8; ks++) {
            u32 a0[4], a1[4];
            {
                u32 u = ((u32)(ks * 2) + aK) ^ aX;
                u32 addr = aAddr0 + (u << 4);
                ldsm4(a0, addr);                       // A0 (hi split)
                if (split == 0) ldsm4(a1, addr + 32768); // A1 (lo split)
            }
            u32 bu = ((u32)(ks * 2) + bK) ^ bX;
            u32 bBase = ring + bRow * 256 + (bu << 4);
            #pragma unroll
            for (int p = 0; p < 8; p++) {
                u32 b[4];
                ldsm4(b, bBase + (u32)p * 4096);
                mma16816(acc[2*p],     a0, b[0], b[1]);
                mma16816(acc[2*p + 1], a0, b[2], b[3]);
                if (split == 0) {
                    mma16816(acc[2*p],     a1, b[0], b[1]);
                    mma16816(acc[2*p + 1], a1, b[2], b[3]);
                }
            }
        }

        if (split == 1) {
            // ---- fold chunk into register finals (lane-local, no atomics) ----
            const int chunk = (t >> 1) & 7;
            const int kh = t >> 4;
            const int bsel = chunk >> 1;
            const int ibase = (chunk & 1) << 3;
            const int e0 = m0 + (lane >> 2);
            #pragma unroll
            for (int nt = 0; nt < 16; nt++) {
                const int i = ibase + (nt >> 1);
                const int qb = (nt & 1) << 1;
                float b2v0 = 0.f, b2v1 = 0.f;
                if (kh == 0) {
                    const int nb = chunk * 128 + nt * 8 + (lane & 3) * 2;
                    b2v0 = smf[B2S_F + nb];
                    b2v1 = smf[B2S_F + nb + 1];
                }
                #pragma unroll
                for (int eh = 0; eh < 2; eh++) {
                    const int e = e0 + eh * 8;
                    const float w0 = acc[nt][eh*2 + 0] + b2v0;
                    const float w1 = acc[nt][eh*2 + 1] + b2v1;
                    if (bsel == 0) {
                        float L = smf[LSS_F + e*16 + i];
                        osum[eh][qb]   += L * w0;
                        osum[eh][qb+1] += L * w1;
                    } else if (bsel == 1) {
                        float L = smf[LVV_F + e*16 + i];
                        osum[eh][qb]   += L * w0;
                        osum[eh][qb+1] += L * w1;
                    } else if (bsel == 2) {
                        float L = smf[LSV_F + e*16 + i];
                        tsv[eh][qb]   += L * w0;
                        tsv[eh][qb+1] += L * w1;
                    } else {
                        float L0 = smf[LVS_F + e*48 + i*3 + 0];
                        float L1 = smf[LVS_F + e*48 + i*3 + 1];
                        float L2 = smf[LVS_F + e*48 + i*3 + 2];
                        rvs[eh][qb][0]   += L0 * w0;
                        rvs[eh][qb][1]   += L1 * w0;
                        rvs[eh][qb][2]   += L2 * w0;
                        rvs[eh][qb+1][0] += L0 * w1;
                        rvs[eh][qb+1][1] += L1 * w1;
                        rvs[eh][qb+1][2] += L2 * w1;
                    }
                }
            }
        }
    }

    // ---- final combine + scatter (from registers) ----
    #pragma unroll
    for (int eh = 0; eh < 2; eh++) {
        const int e = m0 + (lane >> 2) + eh * 8;
        const int eg = eb + e;
        if (eg < E) {
            const int dst = edst[eg];
            float* ob = out + (size_t)dst * 64;
            const float y1a = smf[Y1_F + e*4 + 0];
            const float y1b = smf[Y1_F + e*4 + 1];
            const float y1c = smf[Y1_F + e*4 + 2];
            #pragma unroll
            for (int q = 0; q < 4; q++) {
                const int j = ((q >> 1) << 3) + (lane & 3) * 2 + (q & 1);
                atomicAdd(&ob[j], scl * osum[eh][q]);
                atomicAdd(&ob[16 + j*3 + 0], scl * (tsv[eh][q] * y1a + rvs[eh][q][0]));
                atomicAdd(&ob[16 + j*3 + 1], scl * (tsv[eh][q] * y1b + rvs[eh][q][1]));
                atomicAdd(&ob[16 + j*3 + 2], scl * (tsv[eh][q] * y1c + rvs[eh][q][2]));
            }
        }
    }
}

extern "C" void kernel_launch(void* const* d_in, const int* in_sizes, int n_in,
                              void* d_out, int out_size) {
    const float* nodef = (const float*)d_in[0];
    const float* eattr = (const float*)d_in[1];
    const float* eemb  = (const float*)d_in[2];
    const float* W1    = (const float*)d_in[3];
    const float* b1    = (const float*)d_in[4];
    const float* W2    = (const float*)d_in[5];
    const float* b2    = (const float*)d_in[6];
    const int*   esrc  = (const int*)d_in[7];
    const int*   edst  = (const int*)d_in[8];
    float* out = (float*)d_out;

    int E  = in_sizes[7];
    int Nn = out_size / 64;
    const float cS = 0.17677669529663688110f;  // sqrt(1/32)
    float scl = cS / sqrtf((float)E / (float)Nn);

    cudaMemsetAsync(d_out, 0, (size_t)out_size * sizeof(float));
    prep_w2<<<1024, 256>>>(W2);

    cudaFuncSetAttribute(nequip_mma, cudaFuncAttributeMaxDynamicSharedMemorySize, SMEM_BYTES);
    int grid = (E + TE - 1) / TE;
    nequip_mma<<<grid, 256, SMEM_BYTES>>>(nodef, eattr, eemb, W1, b1, b2,
                                          esrc, edst, out, E, scl);
}

// round 7
// speedup vs baseline: 8.4569x; 2.0796x over previous
#include <cuda_runtime.h>
#include <cuda_fp16.h>
#include <math.h>

typedef unsigned u32;
typedef unsigned long long u64;

#define TE 128

// Pre-swizzled fp16 W2 tile images: [ktile(2)][chunk(8)][128n x 128k fp16 = 32KB]
__device__ __align__(16) __half g_B[2][8][16384];

// ---------------- helpers ----------------
__device__ __forceinline__ u32 smem_u32(const void* p) {
    u32 a; asm("{ .reg .u64 t; cvta.to.shared.u64 t, %1; cvt.u32.u64 %0, t; }" : "=r"(a) : "l"(p));
    return a;
}
__device__ __forceinline__ void cp16(u32 dst, const void* src) {
    asm volatile("cp.async.cg.shared.global [%0], [%1], 16;" :: "r"(dst), "l"(src));
}
__device__ __forceinline__ void cp_commit() { asm volatile("cp.async.commit_group;"); }
template<int N> __device__ __forceinline__ void cp_wait() {
    asm volatile("cp.async.wait_group %0;" :: "n"(N));
}
__device__ __forceinline__ void ldsm4(u32* r, u32 addr) {
    asm volatile("ldmatrix.sync.aligned.m8n8.x4.shared.b16 {%0,%1,%2,%3}, [%4];"
        : "=r"(r[0]), "=r"(r[1]), "=r"(r[2]), "=r"(r[3]) : "r"(addr));
}
__device__ __forceinline__ void mma16816(float* d, const u32* a, u32 b0, u32 b1) {
    asm volatile("mma.sync.aligned.m16n8k16.row.col.f32.f16.f16.f32 "
        "{%0,%1,%2,%3}, {%4,%5,%6,%7}, {%8,%9}, {%0,%1,%2,%3};"
        : "+f"(d[0]), "+f"(d[1]), "+f"(d[2]), "+f"(d[3])
        : "r"(a[0]), "r"(a[1]), "r"(a[2]), "r"(a[3]), "r"(b0), "r"(b1));
}

// ---------------- smem layout ----------------
// bytes:
#define RING_B 0          // 2 stages x 32768
#define HS_B   65536      // A image: 128 edges x 256 k fp16 = 64KB (512B rows)
// float offsets (from smem base; region starts at byte 131072):
#define W1S_F  32768      // [18][256]
#define B1S_F  37376      // 256
#define B2S_F  37632      // 1024
#define EMBS_F 38656      // 128*18
#define LSS_F  40960      // 128*16
#define LVV_F  43008
#define LSV_F  45056
#define LVS_F  47104      // 128*48
#define Y1_F   53248      // 128*4
#define SMEM_BYTES 215040

// ---------------- prep: fp16 convert + swizzle W2 ----------------
__global__ void prep_w2(const float* __restrict__ W2) {
    int idx = blockIdx.x * blockDim.x + threadIdx.x;
    if (idx >= 256 * 1024) return;
    int k = idx >> 10, n = idx & 1023;
    __half v = __float2half(W2[idx]);
    int kt = k >> 7, kl = k & 127, chunk = n >> 7, nl = n & 127;
    int off = nl * 256 + (((kl >> 3) ^ (nl & 7)) << 4) + (kl & 7) * 2;  // bytes
    g_B[kt][chunk][off >> 1] = v;
}

// ---------------- h compute (full K=256, fp16 out) ----------------
__device__ __forceinline__ void compute_h(float* smf, char* smem, int tid) {
    const int e = tid & 127;
    const int ch = tid >> 7;           // column half (128 cols each)
    float er[18];
    #pragma unroll
    for (int t = 0; t < 18; t++) er[t] = smf[EMBS_F + e * 18 + t];
    const int cbase = ch * 128;
    #pragma unroll 2
    for (int cc = 0; cc < 128; cc += 2) {
        const int c = cbase + cc;              // k in [0,256)
        float h[2];
        #pragma unroll
        for (int u = 0; u < 2; u++) {
            float a = smf[B1S_F + c + u];
            #pragma unroll
            for (int t = 0; t < 18; t++)
                a = fmaf(er[t], smf[W1S_F + t * 256 + c + u], a);
            h[u] = a / (1.f + __expf(-a));
        }
        __half2 hp; hp.x = __float2half(h[0]); hp.y = __float2half(h[1]);
        u32 off = (u32)(e * 512 + (((c >> 3) ^ (e & 7)) << 4) + (c & 7) * 2);
        *(u32*)(smem + HS_B + off) = *(u32*)&hp;
    }
}

// ---------------- main kernel ----------------
__global__ __launch_bounds__(256, 1)
void nequip_mma(const float* __restrict__ nodef,
                const float* __restrict__ eattr,
                const float* __restrict__ eemb,
                const float* __restrict__ W1,
                const float* __restrict__ bias1,
                const float* __restrict__ b2,
                const int* __restrict__ esrc,
                const int* __restrict__ edst,
                float* __restrict__ out,
                int E, float scl)
{
    extern __shared__ char smem[];
    float* smf = (float*)smem;
    const u32 sb = smem_u32(smem);
    const int tid = threadIdx.x;
    const int wid = tid >> 5, lane = tid & 31;
    const int wgtid = tid & 127, wg = tid >> 7;
    const int eb = blockIdx.x * TE;

    // ---- stage constants ----
    for (int i = tid; i < 18 * 256; i += 256) smf[W1S_F + i] = W1[i];
    smf[B1S_F + tid] = bias1[tid];
    for (int i = tid; i < 1024; i += 256) smf[B2S_F + i] = b2[i];
    for (int i = tid; i < 128 * 18; i += 256) {
        int g = eb * 18 + i;
        smf[EMBS_F + i] = (g < E * 18) ? eemb[g] : 0.f;
    }

    // ---- per-edge left vectors ----
    {
        const int eg = eb + wgtid;
        if (eg < E) {
            const float inv3 = 0.57735026918962576451f;
            int src = esrc[eg];
            const float* x = nodef + (size_t)src * 64;
            float4 ya = *(const float4*)(eattr + (size_t)eg * 4);
            if (wg == 0) {
                smf[Y1_F + wgtid*4 + 0] = ya.y;
                smf[Y1_F + wgtid*4 + 1] = ya.z;
                smf[Y1_F + wgtid*4 + 2] = ya.w;
            }
            float4 s0 = *(const float4*)(x + wg*8);
            float4 s1 = *(const float4*)(x + wg*8 + 4);
            float sv[8] = {s0.x,s0.y,s0.z,s0.w,s1.x,s1.y,s1.z,s1.w};
            float vv[24];
            const float4* vx = (const float4*)(x + 16 + wg*24);
            #pragma unroll
            for (int q = 0; q < 6; q++) {
                float4 t = vx[q];
                vv[q*4] = t.x; vv[q*4+1] = t.y; vv[q*4+2] = t.z; vv[q*4+3] = t.w;
            }
            #pragma unroll
            for (int il = 0; il < 8; il++) {
                int i = wg*8 + il;
                smf[LSS_F + wgtid*16 + i] = ya.x * sv[il];
                smf[LSV_F + wgtid*16 + i] = sv[il];
                smf[LVV_F + wgtid*16 + i] =
                    inv3 * (ya.y*vv[il*3] + ya.z*vv[il*3+1] + ya.w*vv[il*3+2]);
                smf[LVS_F + wgtid*48 + i*3 + 0] = ya.x * vv[il*3 + 0];
                smf[LVS_F + wgtid*48 + i*3 + 1] = ya.x * vv[il*3 + 1];
                smf[LVS_F + wgtid*48 + i*3 + 2] = ya.x * vv[il*3 + 2];
            }
        }
    }

    // ---- prologue: issue B tile 0 (kt0, chunk0) ----
    {
        const char* src = (const char*)&g_B[0][0][0];
        #pragma unroll
        for (int jj = 0; jj < 8; jj++) {
            int seg = tid + 256 * jj;
            cp16(sb + RING_B + seg * 16, src + seg * 16);
        }
        cp_commit();
    }
    __syncthreads();        // staged constants visible
    compute_h(smf, smem, tid);

    // ---- per-lane state ----
    const int m0 = wid * 16;
    const u32 aRow = (u32)(m0 + (lane & 15));
    const u32 aK   = (u32)(lane >> 4);           // +0/+1 k-unit
    const u32 aAddr0 = sb + HS_B + aRow * 512;
    const u32 bRow = (u32)(((lane >> 4) << 3) + (lane & 7));
    const u32 bK   = (u32)((lane >> 3) & 1);
    const u32 bX   = bRow & 7;

    float acc[16][4];
    float osum[2][4], tsv[2][4], rvs[2][4][3];
    #pragma unroll
    for (int eh = 0; eh < 2; eh++)
        #pragma unroll
        for (int q = 0; q < 4; q++) {
            osum[eh][q] = 0.f; tsv[eh][q] = 0.f;
            rvs[eh][q][0] = 0.f; rvs[eh][q][1] = 0.f; rvs[eh][q][2] = 0.f;
        }

    // ---- main pipeline: 16 tiles = 8 chunk x 2 ktile ----
    for (int t = 0; t < 16; t++) {
        cp_wait<0>();
        __syncthreads();                 // tile t visible; tile t-1 readers done
        if (t + 1 < 16) {
            const int t1 = t + 1;
            const int kt1 = t1 & 1, ch1 = t1 >> 1;
            const char* src = (const char*)&g_B[kt1][ch1][0];
            const u32 dst = sb + RING_B + ((u32)(t1 & 1)) * 32768;
            #pragma unroll
            for (int jj = 0; jj < 8; jj++) {
                int seg = tid + 256 * jj;
                cp16(dst + seg * 16, src + seg * 16);
            }
            cp_commit();
        }

        const int kt = t & 1;
        const u32 ring = sb + RING_B + ((u32)(t & 1)) * 32768;

        if (kt == 0) {
            #pragma unroll
            for (int nt = 0; nt < 16; nt++)
                #pragma unroll
                for (int q = 0; q < 4; q++) acc[nt][q] = 0.f;
        }

        #pragma unroll 2
        for (int ks = 0; ks < 8; ks++) {
            u32 a0[4];
            {
                u32 ku = (u32)(kt * 16 + ks * 2) + aK;       // 16B-unit 0..31
                u32 swz = (ku & ~7u) | ((ku ^ aRow) & 7u);
                ldsm4(a0, aAddr0 + (swz << 4));
            }
            u32 bu = ((u32)(ks * 2) + bK) ^ bX;
            u32 bBase = ring + bRow * 256 + (bu << 4);
            #pragma unroll
            for (int p = 0; p < 8; p++) {
                u32 b[4];
                ldsm4(b, bBase + (u32)p * 4096);
                mma16816(acc[2*p],     a0, b[0], b[1]);
                mma16816(acc[2*p + 1], a0, b[2], b[3]);
            }
        }

        if (kt == 1) {
            // ---- fold chunk into register finals (lane-local, no atomics) ----
            const int chunk = t >> 1;
            const int bsel = chunk >> 1;
            const int ibase = (chunk & 1) << 3;
            const int e0 = m0 + (lane >> 2);
            #pragma unroll
            for (int nt = 0; nt < 16; nt++) {
                const int i = ibase + (nt >> 1);
                const int qb = (nt & 1) << 1;
                const int nb = chunk * 128 + nt * 8 + (lane & 3) * 2;
                const float b2v0 = smf[B2S_F + nb];
                const float b2v1 = smf[B2S_F + nb + 1];
                #pragma unroll
                for (int eh = 0; eh < 2; eh++) {
                    const int e = e0 + eh * 8;
                    const float w0 = acc[nt][eh*2 + 0] + b2v0;
                    const float w1 = acc[nt][eh*2 + 1] + b2v1;
                    if (bsel == 0) {
                        float L = smf[LSS_F + e*16 + i];
                        osum[eh][qb]   += L * w0;
                        osum[eh][qb+1] += L * w1;
                    } else if (bsel == 1) {
                        float L = smf[LVV_F + e*16 + i];
                        osum[eh][qb]   += L * w0;
                        osum[eh][qb+1] += L * w1;
                    } else if (bsel == 2) {
                        float L = smf[LSV_F + e*16 + i];
                        tsv[eh][qb]   += L * w0;
                        tsv[eh][qb+1] += L * w1;
                    } else {
                        float L0 = smf[LVS_F + e*48 + i*3 + 0];
                        float L1 = smf[LVS_F + e*48 + i*3 + 1];
                        float L2 = smf[LVS_F + e*48 + i*3 + 2];
                        rvs[eh][qb][0]   += L0 * w0;
                        rvs[eh][qb][1]   += L1 * w0;
                        rvs[eh][qb][2]   += L2 * w0;
                        rvs[eh][qb+1][0] += L0 * w1;
                        rvs[eh][qb+1][1] += L1 * w1;
                        rvs[eh][qb+1][2] += L2 * w1;
                    }
                }
            }
        }
    }

    // ---- final combine + scatter (from registers) ----
    #pragma unroll
    for (int eh = 0; eh < 2; eh++) {
        const int e = m0 + (lane >> 2) + eh * 8;
        const int eg = eb + e;
        if (eg < E) {
            const int dst = edst[eg];
            float* ob = out + (size_t)dst * 64;
            const float y1a = smf[Y1_F + e*4 + 0];
            const float y1b = smf[Y1_F + e*4 + 1];
            const float y1c = smf[Y1_F + e*4 + 2];
            #pragma unroll
            for (int q = 0; q < 4; q++) {
                const int j = ((q >> 1) << 3) + (lane & 3) * 2 + (q & 1);
                atomicAdd(&ob[j], scl * osum[eh][q]);
                atomicAdd(&ob[16 + j*3 + 0], scl * (tsv[eh][q] * y1a + rvs[eh][q][0]));
                atomicAdd(&ob[16 + j*3 + 1], scl * (tsv[eh][q] * y1b + rvs[eh][q][1]));
                atomicAdd(&ob[16 + j*3 + 2], scl * (tsv[eh][q] * y1c + rvs[eh][q][2]));
            }
        }
    }
}

extern "C" void kernel_launch(void* const* d_in, const int* in_sizes, int n_in,
                              void* d_out, int out_size) {
    const float* nodef = (const float*)d_in[0];
    const float* eattr = (const float*)d_in[1];
    const float* eemb  = (const float*)d_in[2];
    const float* W1    = (const float*)d_in[3];
    const float* b1    = (const float*)d_in[4];
    const float* W2    = (const float*)d_in[5];
    const float* b2    = (const float*)d_in[6];
    const int*   esrc  = (const int*)d_in[7];
    const int*   edst  = (const int*)d_in[8];
    float* out = (float*)d_out;

    int E  = in_sizes[7];
    int Nn = out_size / 64;
    const float cS = 0.17677669529663688110f;  // sqrt(1/32)
    float scl = cS / sqrtf((float)E / (float)Nn);

    cudaMemsetAsync(d_out, 0, (size_t)out_size * sizeof(float));
    prep_w2<<<1024, 256>>>(W2);

    cudaFuncSetAttribute(nequip_mma, cudaFuncAttributeMaxDynamicSharedMemorySize, SMEM_BYTES);
    int grid = (E + TE - 1) / TE;
    nequip_mma<<<grid, 256, SMEM_BYTES>>>(nodef, eattr, eemb, W1, b1, b2,
                                          esrc, edst, out, E, scl);
}

// round 9
// speedup vs baseline: 10.0418x; 1.1874x over previous
#include <cuda_runtime.h>
#include <cuda_fp16.h>
#include <math.h>

typedef unsigned u32;
typedef unsigned long long u64;

#define TE 128

// Pre-swizzled fp16 W2 tile images: [ktile(2)][chunk(8)][128n x 128k fp16 = 32KB]
__device__ __align__(16) __half g_B[2][8][16384];

// ---------------- helpers ----------------
__device__ __forceinline__ u32 smem_u32(const void* p) {
    u32 a; asm("{ .reg .u64 t; cvta.to.shared.u64 t, %1; cvt.u32.u64 %0, t; }" : "=r"(a) : "l"(p));
    return a;
}
__device__ __forceinline__ void cp16(u32 dst, const void* src) {
    asm volatile("cp.async.cg.shared.global [%0], [%1], 16;" :: "r"(dst), "l"(src));
}
__device__ __forceinline__ void cp_commit() { asm volatile("cp.async.commit_group;"); }
template<int N> __device__ __forceinline__ void cp_wait() {
    asm volatile("cp.async.wait_group %0;" :: "n"(N));
}
__device__ __forceinline__ void ldsm4(u32* r, u32 addr) {
    asm volatile("ldmatrix.sync.aligned.m8n8.x4.shared.b16 {%0,%1,%2,%3}, [%4];"
        : "=r"(r[0]), "=r"(r[1]), "=r"(r[2]), "=r"(r[3]) : "r"(addr));
}
__device__ __forceinline__ void mma16816(float* d, const u32* a, u32 b0, u32 b1) {
    asm volatile("mma.sync.aligned.m16n8k16.row.col.f32.f16.f16.f32 "
        "{%0,%1,%2,%3}, {%4,%5,%6,%7}, {%8,%9}, {%0,%1,%2,%3};"
        : "+f"(d[0]), "+f"(d[1]), "+f"(d[2]), "+f"(d[3])
        : "r"(a[0]), "r"(a[1]), "r"(a[2]), "r"(a[3]), "r"(b0), "r"(b1));
}

// ---------------- smem layout ----------------
// bytes:
#define RING_B 0          // 2 stages x 32768
#define HS_B   65536      // A image: 128 edges x 256 k fp16 = 64KB (512B rows)
// float offsets (from smem base; region starts at byte 131072):
#define W1S_F  32768      // [18][256]
#define B1S_F  37376      // 256
#define B2S_F  37632      // 1024
#define EMBS_F 38656      // 128*18
#define LSS_F  40960      // 128*16
#define LVV_F  43008
#define LSV_F  45056
#define LVS_F  47104      // 128*48
#define Y1_F   53248      // 128*4
#define SMEM_BYTES 215040

// ---------------- prep: fp16 convert + swizzle W2 ----------------
__global__ void prep_w2(const float* __restrict__ W2) {
    int idx = blockIdx.x * blockDim.x + threadIdx.x;
    if (idx >= 256 * 1024) return;
    int k = idx >> 10, n = idx & 1023;
    __half v = __float2half(W2[idx]);
    int kt = k >> 7, kl = k & 127, chunk = n >> 7, nl = n & 127;
    int off = nl * 256 + (((kl >> 3) ^ (nl & 7)) << 4) + (kl & 7) * 2;  // bytes
    g_B[kt][chunk][off >> 1] = v;
}

// ---------------- h compute (full K=256, fp16 out) ----------------
__device__ __forceinline__ void compute_h(float* smf, char* smem, int tid) {
    const int e = tid & 127;
    const int ch = tid >> 7;           // column half (128 cols each)
    float er[18];
    #pragma unroll
    for (int t = 0; t < 18; t++) er[t] = smf[EMBS_F + e * 18 + t];
    const int cbase = ch * 128;
    #pragma unroll 2
    for (int cc = 0; cc < 128; cc += 2) {
        const int c = cbase + cc;              // k in [0,256)
        float h[2];
        #pragma unroll
        for (int u = 0; u < 2; u++) {
            float a = smf[B1S_F + c + u];
            #pragma unroll
            for (int t = 0; t < 18; t++)
                a = fmaf(er[t], smf[W1S_F + t * 256 + c + u], a);
            h[u] = a / (1.f + __expf(-a));
        }
        __half2 hp; hp.x = __float2half(h[0]); hp.y = __float2half(h[1]);
        u32 off = (u32)(e * 512 + (((c >> 3) ^ (e & 7)) << 4) + (c & 7) * 2);
        *(u32*)(smem + HS_B + off) = *(u32*)&hp;
    }
}

// prefetch one B tile (tt = chunk*2 + kt) into ring slot (tt&1)
__device__ __forceinline__ void prefetch_tile(u32 sb, int tt, int tid) {
    const char* src = (const char*)&g_B[tt & 1][tt >> 1][0];
    const u32 dst = sb + RING_B + ((u32)(tt & 1)) * 32768;
    #pragma unroll
    for (int jj = 0; jj < 8; jj++) {
        int seg = tid + 256 * jj;
        cp16(dst + seg * 16, src + seg * 16);
    }
    cp_commit();
}

// ---------------- main kernel ----------------
__global__ __launch_bounds__(256, 1)
void nequip_mma(const float* __restrict__ nodef,
                const float* __restrict__ eattr,
                const float* __restrict__ eemb,
                const float* __restrict__ W1,
                const float* __restrict__ bias1,
                const float* __restrict__ b2,
                const int* __restrict__ esrc,
                const int* __restrict__ edst,
                float* __restrict__ out,
                int E, float scl)
{
    extern __shared__ char smem[];
    float* smf = (float*)smem;
    const u32 sb = smem_u32(smem);
    const int tid = threadIdx.x;
    const int wid = tid >> 5, lane = tid & 31;
    const int wgtid = tid & 127, wg = tid >> 7;
    const int eb = blockIdx.x * TE;

    // ---- stage constants via cp.async ----
    {
        const u32 w1dst = sb + W1S_F * 4;
        #pragma unroll
        for (int i = tid; i < 1152; i += 256) cp16(w1dst + i * 16, (const char*)W1 + i * 16);
        const u32 b1dst = sb + B1S_F * 4;
        if (tid < 64) cp16(b1dst + tid * 16, (const char*)bias1 + tid * 16);
        const u32 b2dst = sb + B2S_F * 4;
        if (tid < 256) cp16(b2dst + tid * 16, (const char*)b2 + tid * 16);
        if (eb + TE <= E) {
            const u32 emdst = sb + EMBS_F * 4;
            const char* emsrc = (const char*)(eemb + (size_t)eb * 18);
            #pragma unroll
            for (int i = tid; i < 576; i += 256) cp16(emdst + i * 16, emsrc + i * 16);
        } else {
            for (int i = tid; i < TE * 18; i += 256) {
                int g = eb * 18 + i;
                smf[EMBS_F + i] = (g < E * 18) ? eemb[g] : 0.f;
            }
        }
        prefetch_tile(sb, 0, tid);   // tile 0 in same commit stream (2 groups total)
    }

    // ---- per-edge left vectors (LDG gather, overlaps the copies) ----
    {
        const int eg = eb + wgtid;
        if (eg < E) {
            const float inv3 = 0.57735026918962576451f;
            int src = esrc[eg];
            const float* x = nodef + (size_t)src * 64;
            float4 ya = *(const float4*)(eattr + (size_t)eg * 4);
            if (wg == 0) {
                smf[Y1_F + wgtid*4 + 0] = ya.y;
                smf[Y1_F + wgtid*4 + 1] = ya.z;
                smf[Y1_F + wgtid*4 + 2] = ya.w;
            }
            float4 s0 = *(const float4*)(x + wg*8);
            float4 s1 = *(const float4*)(x + wg*8 + 4);
            float sv[8] = {s0.x,s0.y,s0.z,s0.w,s1.x,s1.y,s1.z,s1.w};
            float vv[24];
            const float4* vx = (const float4*)(x + 16 + wg*24);
            #pragma unroll
            for (int q = 0; q < 6; q++) {
                float4 t = vx[q];
                vv[q*4] = t.x; vv[q*4+1] = t.y; vv[q*4+2] = t.z; vv[q*4+3] = t.w;
            }
            #pragma unroll
            for (int il = 0; il < 8; il++) {
                int i = wg*8 + il;
                smf[LSS_F + wgtid*16 + i] = ya.x * sv[il];
                smf[LSV_F + wgtid*16 + i] = sv[il];
                smf[LVV_F + wgtid*16 + i] =
                    inv3 * (ya.y*vv[il*3] + ya.z*vv[il*3+1] + ya.w*vv[il*3+2]);
                smf[LVS_F + wgtid*48 + i*3 + 0] = ya.x * vv[il*3 + 0];
                smf[LVS_F + wgtid*48 + i*3 + 1] = ya.x * vv[il*3 + 1];
                smf[LVS_F + wgtid*48 + i*3 + 2] = ya.x * vv[il*3 + 2];
            }
        }
    }

    cp_wait<0>();
    __syncthreads();        // constants + tile0 visible
    compute_h(smf, smem, tid);

    // ---- per-lane state: warp = (wm 4) x (wn 2); tile m32 x n64 ----
    const int wm = wid >> 1, wn = wid & 1;
    const int m0 = wm * 32;
    const u32 aR0 = (u32)(m0 + (lane & 15));
    const u32 aX  = aR0 & 7;                       // (aR0+16)&7 == aR0&7
    const u32 aAddr0 = sb + HS_B + aR0 * 512;
    const u32 aAddr1 = aAddr0 + 16 * 512;
    const u32 aK  = (u32)(lane >> 4);
    const u32 bRow = (u32)(((lane >> 4) << 3) + (lane & 7));
    const u32 bK   = (u32)((lane >> 3) & 1);
    const u32 bX   = bRow & 7;
    const u32 bBase0 = sb + RING_B + bRow * 256 + (u32)(wn * 4) * 4096;

    float acc[2][8][4];
    float fo[4][4], ft[4][4], fr[4][4][3];
    #pragma unroll
    for (int me = 0; me < 4; me++)
        #pragma unroll
        for (int q = 0; q < 4; q++) {
            fo[me][q] = 0.f; ft[me][q] = 0.f;
            fr[me][q][0] = 0.f; fr[me][q][1] = 0.f; fr[me][q][2] = 0.f;
        }

    // ---- main loop: 8 chunks x 2 k-tiles ----
    for (int c = 0; c < 8; c++) {
        // ----- phase kt=0 (ring buf 0) -----
        cp_wait<0>();
        __syncthreads();
        prefetch_tile(sb, c * 2 + 1, tid);
        #pragma unroll
        for (int mf = 0; mf < 2; mf++)
            #pragma unroll
            for (int nt = 0; nt < 8; nt++)
                #pragma unroll
                for (int q = 0; q < 4; q++) acc[mf][nt][q] = 0.f;
        #pragma unroll
        for (int ks = 0; ks < 8; ks++) {
            u32 a0[4], a1[4];
            u32 ku = (u32)(ks * 2) + aK;
            u32 swz = (ku & ~7u) | ((ku ^ aX) & 7u);
            ldsm4(a0, aAddr0 + (swz << 4));
            ldsm4(a1, aAddr1 + (swz << 4));
            u32 bu = ((u32)(ks * 2) + bK) ^ bX;
            #pragma unroll
            for (int pl = 0; pl < 4; pl++) {
                u32 b[4];
                ldsm4(b, bBase0 + (bu << 4) + (u32)pl * 4096);
                mma16816(acc[0][pl*2],     a0, b[0], b[1]);
                mma16816(acc[0][pl*2 + 1], a0, b[2], b[3]);
                mma16816(acc[1][pl*2],     a1, b[0], b[1]);
                mma16816(acc[1][pl*2 + 1], a1, b[2], b[3]);
            }
        }
        // ----- phase kt=1 (ring buf 1) -----
        cp_wait<0>();
        __syncthreads();
        if (c < 7) prefetch_tile(sb, c * 2 + 2, tid);
        #pragma unroll
        for (int ks = 0; ks < 8; ks++) {
            u32 a0[4], a1[4];
            u32 ku = (u32)(16 + ks * 2) + aK;
            u32 swz = (ku & ~7u) | ((ku ^ aX) & 7u);
            ldsm4(a0, aAddr0 + (swz << 4));
            ldsm4(a1, aAddr1 + (swz << 4));
            u32 bu = ((u32)(ks * 2) + bK) ^ bX;
            #pragma unroll
            for (int pl = 0; pl < 4; pl++) {
                u32 b[4];
                ldsm4(b, bBase0 + 32768 + (bu << 4) + (u32)pl * 4096);
                mma16816(acc[0][pl*2],     a0, b[0], b[1]);
                mma16816(acc[0][pl*2 + 1], a0, b[2], b[3]);
                mma16816(acc[1][pl*2],     a1, b[0], b[1]);
                mma16816(acc[1][pl*2 + 1], a1, b[2], b[3]);
            }
        }
        // ----- fold chunk into register finals -----
        {
            const int bsel = c >> 1;
            const int ibase = (c & 1) << 3;
            #pragma unroll
            for (int mf = 0; mf < 2; mf++) {
                #pragma unroll
                for (int ntl = 0; ntl < 8; ntl++) {
                    const int nt = wn * 8 + ntl;
                    const int i = ibase + wn * 4 + (ntl >> 1);
                    const int nb = c * 128 + nt * 8 + (lane & 3) * 2;
                    const float b2v0 = smf[B2S_F + nb];
                    const float b2v1 = smf[B2S_F + nb + 1];
                    const int qb = (nt & 1) << 1;
                    #pragma unroll
                    for (int eh = 0; eh < 2; eh++) {
                        const int me = mf * 2 + eh;
                        const int e = m0 + mf * 16 + (lane >> 2) + eh * 8;
                        const float w0 = acc[mf][ntl][eh*2 + 0] + b2v0;
                        const float w1 = acc[mf][ntl][eh*2 + 1] + b2v1;
                        if (bsel == 0) {
                            float L = smf[LSS_F + e*16 + i];
                            fo[me][qb]   += L * w0;
                            fo[me][qb+1] += L * w1;
                        } else if (bsel == 1) {
                            float L = smf[LVV_F + e*16 + i];
                            fo[me][qb]   += L * w0;
                            fo[me][qb+1] += L * w1;
                        } else if (bsel == 2) {
                            float L = smf[LSV_F + e*16 + i];
                            ft[me][qb]   += L * w0;
                            ft[me][qb+1] += L * w1;
                        } else {
                            float L0 = smf[LVS_F + e*48 + i*3 + 0];
                            float L1 = smf[LVS_F + e*48 + i*3 + 1];
                            float L2 = smf[LVS_F + e*48 + i*3 + 2];
                            fr[me][qb][0]   += L0 * w0;
                            fr[me][qb][1]   += L1 * w0;
                            fr[me][qb][2]   += L2 * w0;
                            fr[me][qb+1][0] += L0 * w1;
                            fr[me][qb+1][1] += L1 * w1;
                            fr[me][qb+1][2] += L2 * w1;
                        }
                    }
                }
            }
        }
    }

    // ---- final scatter: both n-warps REDG their partials (linear sum) ----
    #pragma unroll
    for (int me = 0; me < 4; me++) {
        const int e = m0 + (me >> 1) * 16 + (lane >> 2) + (me & 1) * 8;
        const int eg = eb + e;
        if (eg < E) {
            const int dst = edst[eg];
            float* ob = out + (size_t)dst * 64;
            const float y1a = smf[Y1_F + e*4 + 0];
            const float y1b = smf[Y1_F + e*4 + 1];
            const float y1c = smf[Y1_F + e*4 + 2];
            #pragma unroll
            for (int q = 0; q < 4; q++) {
                const int j = ((q >> 1) << 3) + (lane & 3) * 2 + (q & 1);
                atomicAdd(&ob[j], scl * fo[me][q]);
                atomicAdd(&ob[16 + j*3 + 0], scl * (ft[me][q] * y1a + fr[me][q][0]));
                atomicAdd(&ob[16 + j*3 + 1], scl * (ft[me][q] * y1b + fr[me][q][1]));
                atomicAdd(&ob[16 + j*3 + 2], scl * (ft[me][q] * y1c + fr[me][q][2]));
            }
        }
    }
}

extern "C" void kernel_launch(void* const* d_in, const int* in_sizes, int n_in,
                              void* d_out, int out_size) {
    const float* nodef = (const float*)d_in[0];
    const float* eattr = (const float*)d_in[1];
    const float* eemb  = (const float*)d_in[2];
    const float* W1    = (const float*)d_in[3];
    const float* b1    = (const float*)d_in[4];
    const float* W2    = (const float*)d_in[5];
    const float* b2    = (const float*)d_in[6];
    const int*   esrc  = (const int*)d_in[7];
    const int*   edst  = (const int*)d_in[8];
    float* out = (float*)d_out;

    int E  = in_sizes[7];
    int Nn = out_size / 64;
    const float cS = 0.17677669529663688110f;  // sqrt(1/32)
    float scl = cS / sqrtf((float)E / (float)Nn);

    cudaMemsetAsync(d_out, 0, (size_t)out_size * sizeof(float));
    prep_w2<<<1024, 256>>>(W2);

    cudaFuncSetAttribute(nequip_mma, cudaFuncAttributeMaxDynamicSharedMemorySize, SMEM_BYTES);
    int grid = (E + TE - 1) / TE;
    nequip_mma<<<grid, 256, SMEM_BYTES>>>(nodef, eattr, eemb, W1, b1, b2,
                                          esrc, edst, out, E, scl);
}